// round 3
// baseline (speedup 1.0000x reference)
#include <cuda_runtime.h>
#include <math.h>

#define B_  128
#define T_  256
#define F_  512
#define H_  1024
#define G4  4096   // 4*H

// Scratch: xz = x@W + b laid out [T][B][4H]  (536.9 MB), and cell state c [B][H].
__device__ float g_xz[(size_t)T_ * B_ * G4];
__device__ float g_c[(size_t)B_ * H_];

__device__ __forceinline__ float fast_sigmoid(float z) {
    return 1.0f / (1.0f + __expf(-z));
}

// ---------------------------------------------------------------------------
// Kernel A: xz[t][b][n] = sum_f x[b][t][f] * W[f][n] + bias[n]
// Smem-tiled SGEMM: BM=128 (=B, blockIdx.y == t), BN=128, BK=16,
// 256 threads, 8x8 accumulator per thread, LDS.128 fragment loads.
// ---------------------------------------------------------------------------
__global__ __launch_bounds__(256) void xw_kernel(const float* __restrict__ x,
                                                 const float* __restrict__ W,
                                                 const float* __restrict__ bias) {
    const int by = blockIdx.y;          // t index (0..255)
    const int bx = blockIdx.x;          // N tile (0..31)
    const int tid = threadIdx.x;
    const int tx = tid & 15;            // 0..15
    const int ty = tid >> 4;            // 0..15

    // 132-float rows: 528 B = 33*16 B -> every row start is 16B-aligned.
    __shared__ float As[16][132];       // As[k][m] (transposed)
    __shared__ float Bs[16][132];       // Bs[k][n]

    float acc[8][8];
#pragma unroll
    for (int i = 0; i < 8; i++)
#pragma unroll
        for (int j = 0; j < 8; j++) acc[i][j] = 0.0f;

    for (int k0 = 0; k0 < F_; k0 += 16) {
        // A tile: 128 rows (b) x 16 cols (k). Each thread: 2x float4.
#pragma unroll
        for (int i = 0; i < 2; i++) {
            int r = (tid >> 2) + i * 64;         // b index 0..127
            int c = (tid & 3) * 4;               // 0,4,8,12
            const float4 v = *(const float4*)&x[((size_t)r * T_ + by) * F_ + k0 + c];
            As[c + 0][r] = v.x;
            As[c + 1][r] = v.y;
            As[c + 2][r] = v.z;
            As[c + 3][r] = v.w;
        }
        // B tile: 16 rows (k) x 128 cols (n). Each thread: 2x float4.
#pragma unroll
        for (int i = 0; i < 2; i++) {
            int r = (tid >> 5) + i * 8;          // 0..15
            int c = (tid & 31) * 4;              // 0..124
            const float4 v = *(const float4*)&W[(size_t)(k0 + r) * G4 + (size_t)bx * 128 + c];
            *(float4*)&Bs[r][c] = v;
        }
        __syncthreads();

#pragma unroll
        for (int kk = 0; kk < 16; kk++) {
            float4 a0 = *(const float4*)&As[kk][ty * 8];
            float4 a1 = *(const float4*)&As[kk][ty * 8 + 4];
            float4 b0 = *(const float4*)&Bs[kk][tx * 8];
            float4 b1 = *(const float4*)&Bs[kk][tx * 8 + 4];
            float ra[8] = {a0.x, a0.y, a0.z, a0.w, a1.x, a1.y, a1.z, a1.w};
            float rb[8] = {b0.x, b0.y, b0.z, b0.w, b1.x, b1.y, b1.z, b1.w};
#pragma unroll
            for (int i = 0; i < 8; i++)
#pragma unroll
                for (int j = 0; j < 8; j++)
                    acc[i][j] = fmaf(ra[i], rb[j], acc[i][j]);
        }
        __syncthreads();
    }

    // Epilogue: add bias, write to g_xz[t][b][n]
#pragma unroll
    for (int i = 0; i < 8; i++) {
        int r = ty * 8 + i;                                   // b index
        size_t row = ((size_t)by * B_ + r) * G4 + (size_t)bx * 128;
#pragma unroll
        for (int j = 0; j < 8; j++) {
            int c = tx * 8 + j;
            g_xz[row + c] = acc[i][j] + bias[bx * 128 + c];
        }
    }
}

// ---------------------------------------------------------------------------
// Kernel B (per timestep): tile of 8 j-columns x all 4 gates fused.
//   z[b][gate*H + j] = xz_t[b][gate*H + j] + sum_k h_prev[b][k] * U[k][gate*H + j]
// then gates -> c/h update. Grid = 128 blocks (j tiles), 256 threads.
// GEMM view: C[128 x 32] = Hprev[128 x 1024] @ Ublk[1024 x 32].
// Thread tile: 4x4, LDS.128 fragment loads.
// ---------------------------------------------------------------------------
__global__ __launch_bounds__(256) void step_kernel(int t,
                                                   const float* __restrict__ U,
                                                   float* __restrict__ out) {
    const int j0  = blockIdx.x * 8;
    const int tid = threadIdx.x;
    const int tx  = tid & 7;            // 0..7  -> 4 columns each
    const int ty  = tid >> 3;           // 0..31 -> 4 rows each
    const int first = (t == 0);

    const float* xz_t   = g_xz + (size_t)t * B_ * G4;
    const float* h_prev = out + (size_t)(t - 1) * B_ * H_;   // unused when t==0
    float*       h_out  = out + (size_t)t * B_ * H_;

    __shared__ float Hs[32][132];       // Hs[k][b]; 528B rows, 16B-aligned
    __shared__ float Us[32][32];        // Us[k][c]; 128B rows
    __shared__ float Zs[128][36];       // z tile; 144B rows, 16B-aligned

    // column-group -> global U column base: c = tx*4 + j
    const int gate  = tx >> 1;                   // (tx*4)/8
    const int jjb   = (tx & 1) * 4;              // (tx*4)%8
    const int nbase = gate * H_ + j0 + jjb;      // +j (0..3) contiguous

    // acc init = xz (bias already folded in kernel A)
    float acc[4][4];
#pragma unroll
    for (int i = 0; i < 4; i++) {
        int b = ty * 4 + i;
        const float4 v = *(const float4*)&xz_t[(size_t)b * G4 + nbase];
        acc[i][0] = v.x; acc[i][1] = v.y; acc[i][2] = v.z; acc[i][3] = v.w;
    }

    if (!first) {
        for (int k0 = 0; k0 < H_; k0 += 32) {
            // H tile: 128 rows (b) x 32 cols (k), stored transposed Hs[k][b]
#pragma unroll
            for (int i = 0; i < 4; i++) {
                int r  = (tid >> 3) + i * 32;     // b 0..127
                int c4 = (tid & 7) * 4;           // k 0..28
                const float4 v = *(const float4*)&h_prev[(size_t)r * H_ + k0 + c4];
                Hs[c4 + 0][r] = v.x;
                Hs[c4 + 1][r] = v.y;
                Hs[c4 + 2][r] = v.z;
                Hs[c4 + 3][r] = v.w;
            }
            // U tile: 32 rows (k) x 32 block-cols
            {
                int kk = tid >> 3;                // 0..31
                int c4 = tid & 7;
                int g2 = c4 >> 1;
                int jb = (c4 & 1) * 4;
                const float4 v = *(const float4*)&U[(size_t)(k0 + kk) * G4 + g2 * H_ + j0 + jb];
                *(float4*)&Us[kk][c4 * 4] = v;
            }
            __syncthreads();

#pragma unroll
            for (int kk = 0; kk < 32; kk++) {
                float4 hv = *(const float4*)&Hs[kk][ty * 4];
                float4 uv = *(const float4*)&Us[kk][tx * 4];
                float rh[4] = {hv.x, hv.y, hv.z, hv.w};
                float ru[4] = {uv.x, uv.y, uv.z, uv.w};
#pragma unroll
                for (int i = 0; i < 4; i++)
#pragma unroll
                    for (int j = 0; j < 4; j++)
                        acc[i][j] = fmaf(rh[i], ru[j], acc[i][j]);
            }
            __syncthreads();
        }
    }

    // Stage z tile so each thread can gather all 4 gates of a (b,j)
#pragma unroll
    for (int i = 0; i < 4; i++) {
        int r = ty * 4 + i;
#pragma unroll
        for (int j = 0; j < 4; j++) {
            Zs[r][tx * 4 + j] = acc[i][j];
        }
    }
    __syncthreads();

    // Gate math: 128 b x 8 jj = 1024 elements, 4 per thread
#pragma unroll
    for (int i = 0; i < 4; i++) {
        int e  = tid + i * 256;
        int b  = e >> 3;
        int jj = e & 7;
        float zi = Zs[b][jj];
        float zf = Zs[b][8 + jj];
        float zg = Zs[b][16 + jj];
        float zo = Zs[b][24 + jj];

        float ig = fast_sigmoid(zi);
        float fg = fast_sigmoid(zf);
        float gg = tanhf(zg);
        float og = fast_sigmoid(zo);

        size_t idx = (size_t)b * H_ + j0 + jj;
        float c_old = first ? 0.0f : g_c[idx];
        float c_new = fg * c_old + ig * gg;
        float h_new = og * tanhf(c_new);

        g_c[idx]   = c_new;
        h_out[idx] = h_new;
    }
}

// ---------------------------------------------------------------------------
extern "C" void kernel_launch(void* const* d_in, const int* in_sizes, int n_in,
                              void* d_out, int out_size) {
    const float* x = (const float*)d_in[0];   // [B, T, F]
    const float* W = (const float*)d_in[1];   // [F, 4H]
    const float* U = (const float*)d_in[2];   // [H, 4H]
    const float* b = (const float*)d_in[3];   // [4H]
    float* out = (float*)d_out;               // [T, B, H]

    (void)in_sizes; (void)n_in; (void)out_size;

    // Phase 1: xz = x@W + b  (parallel)
    dim3 gridA(G4 / 128, T_);
    xw_kernel<<<gridA, 256>>>(x, W, b);

    // Phase 2: sequential recurrence, one launch per timestep
    for (int t = 0; t < T_; t++) {
        step_kernel<<<128, 256>>>(t, U, out);
    }
}

// round 11
// speedup vs baseline: 1.9391x; 1.9391x over previous
#include <cuda_runtime.h>
#include <cuda_bf16.h>
#include <math.h>
#include <stdint.h>

#define B_  128
#define T_  256
#define F_  512
#define H_  1024
#define G4  4096   // 4*H

// ---------------------------------------------------------------------------
// Scratch — R3-passing set (g_xz, g_c) + 17 MiB for U^T/h in bf16 hi/lo.
// ---------------------------------------------------------------------------
__device__ float         g_xz[(size_t)T_ * B_ * G4];          // 537 MB fp32
__device__ float         g_c[(size_t)B_ * H_];
__device__ __nv_bfloat16 g_Ut_hi[(size_t)G4 * H_];            // U^T [4096][1024]
__device__ __nv_bfloat16 g_Ut_lo[(size_t)G4 * H_];
__device__ __nv_bfloat16 g_h_hi[(size_t)B_ * H_];
__device__ __nv_bfloat16 g_h_lo[(size_t)B_ * H_];

__device__ __forceinline__ float fast_sigmoid(float z) {
    return 1.0f / (1.0f + __expf(-z));
}
__device__ __forceinline__ uint32_t smem_u32(const void* p) {
    uint32_t a;
    asm("{ .reg .u64 t; cvta.to.shared.u64 t, %1; cvt.u32.u64 %0, t; }" : "=r"(a) : "l"(p));
    return a;
}

// All-scalar ldmatrix / mma macros (no array operands anywhere).
#define LDM4(r0, r1, r2, r3, addr)                                            \
    asm volatile("ldmatrix.sync.aligned.m8n8.x4.shared.b16 {%0,%1,%2,%3}, [%4];" \
                 : "=r"(r0), "=r"(r1), "=r"(r2), "=r"(r3) : "r"(addr))
#define MMA(c0, c1, c2, c3, a0, a1, a2, a3, b0, b1)                           \
    asm volatile("mma.sync.aligned.m16n8k16.row.col.f32.bf16.bf16.f32 "       \
                 "{%0,%1,%2,%3}, {%4,%5,%6,%7}, {%8,%9}, {%0,%1,%2,%3};"      \
                 : "+f"(c0), "+f"(c1), "+f"(c2), "+f"(c3)                     \
                 : "r"(a0), "r"(a1), "r"(a2), "r"(a3), "r"(b0), "r"(b1))

// smem tile: 64 bf16/row padded to 144 B -> 8 consecutive rows hit 8 distinct
// 16B banks (144 mod 128 = 16) => conflict-free ldmatrix and STS.
#define RSB   144
#define A_HI  0
#define A_LO  18432
#define B_HI  36864
#define B_LO  41472
#define SMB   46080   // <= 48 KB: static __shared__

// ---------------------------------------------------------------------------
// Prep: U [K=H][N=4H] fp32 -> U^T hi/lo [4H][H] bf16 (tiled transpose + split)
// ---------------------------------------------------------------------------
__global__ __launch_bounds__(256) void transpose_split_kernel(const float* __restrict__ in,
                                                              int K, int N) {
    __shared__ float ts[32][33];
    int k0 = blockIdx.x * 32, n0 = blockIdx.y * 32;
    int r = threadIdx.x >> 5, c = threadIdx.x & 31;
#pragma unroll
    for (int i = 0; i < 4; i++)
        ts[r + i * 8][c] = in[(size_t)(k0 + r + i * 8) * N + n0 + c];
    __syncthreads();
#pragma unroll
    for (int i = 0; i < 4; i++) {
        int n = n0 + r + i * 8;
        float v = ts[c][r + i * 8];
        __nv_bfloat16 hi = __float2bfloat16(v);
        g_Ut_hi[(size_t)n * K + k0 + c] = hi;
        g_Ut_lo[(size_t)n * K + k0 + c] = __float2bfloat16(v - __bfloat162float(hi));
    }
}

// ---------------------------------------------------------------------------
// xw_kernel — VERBATIM the round-3 PASSING fp32 SGEMM (BM=128,BN=128,BK=16).
// ---------------------------------------------------------------------------
__global__ __launch_bounds__(256) void xw_kernel(const float* __restrict__ x,
                                                 const float* __restrict__ W,
                                                 const float* __restrict__ bias) {
    const int by = blockIdx.y;          // t index
    const int bx = blockIdx.x;          // N tile
    const int tid = threadIdx.x;
    const int tx = tid & 15;
    const int ty = tid >> 4;

    __shared__ float As[16][132];
    __shared__ float Bs[16][132];

    float acc[8][8];
#pragma unroll
    for (int i = 0; i < 8; i++)
#pragma unroll
        for (int j = 0; j < 8; j++) acc[i][j] = 0.0f;

    for (int k0 = 0; k0 < F_; k0 += 16) {
#pragma unroll
        for (int i = 0; i < 2; i++) {
            int r = (tid >> 2) + i * 64;
            int c = (tid & 3) * 4;
            const float4 v = *(const float4*)&x[((size_t)r * T_ + by) * F_ + k0 + c];
            As[c + 0][r] = v.x;
            As[c + 1][r] = v.y;
            As[c + 2][r] = v.z;
            As[c + 3][r] = v.w;
        }
#pragma unroll
        for (int i = 0; i < 2; i++) {
            int r = (tid >> 5) + i * 8;
            int c = (tid & 31) * 4;
            const float4 v = *(const float4*)&W[(size_t)(k0 + r) * G4 + (size_t)bx * 128 + c];
            *(float4*)&Bs[r][c] = v;
        }
        __syncthreads();

#pragma unroll
        for (int kk = 0; kk < 16; kk++) {
            float4 a0 = *(const float4*)&As[kk][ty * 8];
            float4 a1 = *(const float4*)&As[kk][ty * 8 + 4];
            float4 b0 = *(const float4*)&Bs[kk][tx * 8];
            float4 b1 = *(const float4*)&Bs[kk][tx * 8 + 4];
            float ra[8] = {a0.x, a0.y, a0.z, a0.w, a1.x, a1.y, a1.z, a1.w};
            float rb[8] = {b0.x, b0.y, b0.z, b0.w, b1.x, b1.y, b1.z, b1.w};
#pragma unroll
            for (int i = 0; i < 8; i++)
#pragma unroll
                for (int j = 0; j < 8; j++)
                    acc[i][j] = fmaf(ra[i], rb[j], acc[i][j]);
        }
        __syncthreads();
    }

#pragma unroll
    for (int i = 0; i < 8; i++) {
        int r = ty * 8 + i;
        size_t row = ((size_t)by * B_ + r) * G4 + (size_t)bx * 128;
#pragma unroll
        for (int j = 0; j < 8; j++) {
            int c = tx * 8 + j;
            g_xz[row + c] = acc[i][j] + bias[bx * 128 + c];
        }
    }
}

// ---------------------------------------------------------------------------
// step kernel (tensor cores, zero local arrays): grid 128 (j-tiles of 8),
// 256 thr.  M=128(batch) x N=32(4 gates x 8 j) x K=1024, 3-pass bf16 hi/lo.
// ---------------------------------------------------------------------------
__global__ __launch_bounds__(256) void step_kernel(int t, float* __restrict__ out) {
    __shared__ __align__(16) char sm[SMB];
    const int tid = threadIdx.x, wid = tid >> 5, lane = tid & 31;
    const int j0 = blockIdx.x * 8;
    const uint32_t sb = smem_u32(sm);
    const int m0 = wid * 16;

    const uint32_t a_off = (uint32_t)((m0 + (lane & 15)) * RSB + (lane >> 4) * 16);
    const uint32_t b_off = (uint32_t)((((lane >> 4) & 1) * 8 + (lane & 7)) * RSB
                                      + ((lane >> 3) & 1) * 16);

    float ci0 = 0.f, ci1 = 0.f, ci2 = 0.f, ci3 = 0.f;
    float cf0 = 0.f, cf1 = 0.f, cf2 = 0.f, cf3 = 0.f;
    float cg0 = 0.f, cg1 = 0.f, cg2 = 0.f, cg3 = 0.f;
    float co0 = 0.f, co1 = 0.f, co2 = 0.f, co3 = 0.f;

    if (t > 0) {
        const int ra = tid >> 3;               // 0..31 (A base row / B row)
        const int k8 = tid & 7;                // 16B chunk within 128B row
        const size_t aoff = (size_t)ra * H_ + k8 * 8;
        const int nb = tid >> 3;               // B: n row 0..31
        const size_t boff = (size_t)((nb >> 3) * H_ + j0 + (nb & 7)) * H_ + k8 * 8;
        const uint32_t sa = (uint32_t)(ra * RSB + k8 * 16);
        const uint32_t sbn = (uint32_t)(nb * RSB + k8 * 16);

        uint4 p0, p1, p2, p3, p4, p5, p6, p7, q0, q1;
        // prefetch k-tile 0
        p0 = *(const uint4*)(g_h_hi + aoff);
        p1 = *(const uint4*)(g_h_hi + aoff + (size_t)32 * H_);
        p2 = *(const uint4*)(g_h_hi + aoff + (size_t)64 * H_);
        p3 = *(const uint4*)(g_h_hi + aoff + (size_t)96 * H_);
        p4 = *(const uint4*)(g_h_lo + aoff);
        p5 = *(const uint4*)(g_h_lo + aoff + (size_t)32 * H_);
        p6 = *(const uint4*)(g_h_lo + aoff + (size_t)64 * H_);
        p7 = *(const uint4*)(g_h_lo + aoff + (size_t)96 * H_);
        q0 = *(const uint4*)(g_Ut_hi + boff);
        q1 = *(const uint4*)(g_Ut_lo + boff);

        for (int kt = 0; kt < 16; kt++) {
            __syncthreads();
            *(uint4*)(sm + A_HI + sa)                = p0;
            *(uint4*)(sm + A_HI + sa + 32 * RSB)     = p1;
            *(uint4*)(sm + A_HI + sa + 64 * RSB)     = p2;
            *(uint4*)(sm + A_HI + sa + 96 * RSB)     = p3;
            *(uint4*)(sm + A_LO + sa)                = p4;
            *(uint4*)(sm + A_LO + sa + 32 * RSB)     = p5;
            *(uint4*)(sm + A_LO + sa + 64 * RSB)     = p6;
            *(uint4*)(sm + A_LO + sa + 96 * RSB)     = p7;
            *(uint4*)(sm + B_HI + sbn)               = q0;
            *(uint4*)(sm + B_LO + sbn)               = q1;
            __syncthreads();
            if (kt + 1 < 16) {
                const size_t ko = (size_t)(kt + 1) * 64;
                p0 = *(const uint4*)(g_h_hi + aoff + ko);
                p1 = *(const uint4*)(g_h_hi + aoff + (size_t)32 * H_ + ko);
                p2 = *(const uint4*)(g_h_hi + aoff + (size_t)64 * H_ + ko);
                p3 = *(const uint4*)(g_h_hi + aoff + (size_t)96 * H_ + ko);
                p4 = *(const uint4*)(g_h_lo + aoff + ko);
                p5 = *(const uint4*)(g_h_lo + aoff + (size_t)32 * H_ + ko);
                p6 = *(const uint4*)(g_h_lo + aoff + (size_t)64 * H_ + ko);
                p7 = *(const uint4*)(g_h_lo + aoff + (size_t)96 * H_ + ko);
                q0 = *(const uint4*)(g_Ut_hi + boff + ko);
                q1 = *(const uint4*)(g_Ut_lo + boff + ko);
            }
#pragma unroll
            for (int s = 0; s < 4; s++) {
                uint32_t ah0, ah1, ah2, ah3, al0, al1, al2, al3;
                uint32_t b0, b1, b2, b3, d0, d1, d2, d3;
                LDM4(ah0, ah1, ah2, ah3, sb + A_HI + a_off + s * 32);
                LDM4(al0, al1, al2, al3, sb + A_LO + a_off + s * 32);
                // n-block 0 (gates i, f)
                LDM4(b0, b1, b2, b3, sb + B_HI + b_off + s * 32);
                LDM4(d0, d1, d2, d3, sb + B_LO + b_off + s * 32);
                MMA(ci0, ci1, ci2, ci3, ah0, ah1, ah2, ah3, b0, b1);
                MMA(ci0, ci1, ci2, ci3, ah0, ah1, ah2, ah3, d0, d1);
                MMA(ci0, ci1, ci2, ci3, al0, al1, al2, al3, b0, b1);
                MMA(cf0, cf1, cf2, cf3, ah0, ah1, ah2, ah3, b2, b3);
                MMA(cf0, cf1, cf2, cf3, ah0, ah1, ah2, ah3, d2, d3);
                MMA(cf0, cf1, cf2, cf3, al0, al1, al2, al3, b2, b3);
                // n-block 1 (gates g, o)
                LDM4(b0, b1, b2, b3, sb + B_HI + b_off + 16 * RSB + s * 32);
                LDM4(d0, d1, d2, d3, sb + B_LO + b_off + 16 * RSB + s * 32);
                MMA(cg0, cg1, cg2, cg3, ah0, ah1, ah2, ah3, b0, b1);
                MMA(cg0, cg1, cg2, cg3, ah0, ah1, ah2, ah3, d0, d1);
                MMA(cg0, cg1, cg2, cg3, al0, al1, al2, al3, b0, b1);
                MMA(co0, co1, co2, co3, ah0, ah1, ah2, ah3, b2, b3);
                MMA(co0, co1, co2, co3, ah0, ah1, ah2, ah3, d2, d3);
                MMA(co0, co1, co2, co3, al0, al1, al2, al3, b2, b3);
            }
        }
    }

    // Epilogue: thread cells (b = m0 + (lane>>2) + 8*rh, j = j0 + (lane&3)*2 + ch)
    const int r = lane >> 2;
    const int cc = (lane & 3) * 2;
    const int first = (t == 0);
#pragma unroll
    for (int rh = 0; rh < 2; rh++) {
        int b = m0 + r + rh * 8;
        const float* xzp = g_xz + ((size_t)t * B_ + b) * G4;
#pragma unroll
        for (int ch = 0; ch < 2; ch++) {
            int j = j0 + cc + ch;
            float zi, zf, zg, zo;
            if (rh == 0 && ch == 0) { zi = ci0; zf = cf0; zg = cg0; zo = co0; }
            else if (rh == 0)       { zi = ci1; zf = cf1; zg = cg1; zo = co1; }
            else if (ch == 0)       { zi = ci2; zf = cf2; zg = cg2; zo = co2; }
            else                    { zi = ci3; zf = cf3; zg = cg3; zo = co3; }
            zi += xzp[0 * H_ + j];
            zf += xzp[1 * H_ + j];
            zg += xzp[2 * H_ + j];
            zo += xzp[3 * H_ + j];
            float ig = fast_sigmoid(zi);
            float fg = fast_sigmoid(zf);
            float gg = tanhf(zg);
            float og = fast_sigmoid(zo);
            size_t idx = (size_t)b * H_ + j;
            float c_old = first ? 0.0f : g_c[idx];
            float cv = fg * c_old + ig * gg;
            float hv = og * tanhf(cv);
            g_c[idx] = cv;
            out[(size_t)t * B_ * H_ + idx] = hv;
            __nv_bfloat16 hi = __float2bfloat16(hv);
            g_h_hi[idx] = hi;
            g_h_lo[idx] = __float2bfloat16(hv - __bfloat162float(hi));
        }
    }
}

// ---------------------------------------------------------------------------
extern "C" void kernel_launch(void* const* d_in, const int* in_sizes, int n_in,
                              void* d_out, int out_size) {
    const float* x = (const float*)d_in[0];   // [B, T, F]
    const float* W = (const float*)d_in[1];   // [F, 4H]
    const float* U = (const float*)d_in[2];   // [H, 4H]
    const float* b = (const float*)d_in[3];   // [4H]
    float* out = (float*)d_out;               // [T, B, H]
    (void)in_sizes; (void)n_in; (void)out_size;

    // Prep (off the serial path)
    transpose_split_kernel<<<dim3(H_ / 32, G4 / 32), 256>>>(U, H_, G4);

    // Phase 1: xz = x@W + b (proven R3 fp32 GEMM)
    dim3 gridA(G4 / 128, T_);
    xw_kernel<<<gridA, 256>>>(x, W, b);

    // Phase 2: recurrence
    for (int t = 0; t < T_; t++) {
        step_kernel<<<128, 256>>>(t, out);
    }
}

// round 12
// speedup vs baseline: 2.3648x; 1.2195x over previous
#include <cuda_runtime.h>
#include <cuda_bf16.h>
#include <math.h>
#include <stdint.h>

#define B_  128
#define T_  256
#define F_  512
#define H_  1024
#define G4  4096   // 4*H

// ---------------------------------------------------------------------------
// Scratch (static __device__; no runtime allocation)
// ---------------------------------------------------------------------------
__device__ float         g_xz[(size_t)T_ * B_ * G4];          // 537 MB fp32
__device__ float         g_c[(size_t)B_ * H_];
__device__ __nv_bfloat16 g_Ut_hi[(size_t)G4 * H_];            // U^T [4096][1024]
__device__ __nv_bfloat16 g_Ut_lo[(size_t)G4 * H_];
__device__ __nv_bfloat16 g_Wt_hi[(size_t)G4 * F_];            // W^T [4096][512]
__device__ __nv_bfloat16 g_Wt_lo[(size_t)G4 * F_];
__device__ __nv_bfloat16 g_x_hi[(size_t)B_ * T_ * F_];
__device__ __nv_bfloat16 g_x_lo[(size_t)B_ * T_ * F_];
__device__ __nv_bfloat16 g_h_hi[(size_t)B_ * H_];
__device__ __nv_bfloat16 g_h_lo[(size_t)B_ * H_];
__device__ unsigned      g_bar;

__device__ __forceinline__ float fast_sigmoid(float z) {
    return 1.0f / (1.0f + __expf(-z));
}
__device__ __forceinline__ uint32_t smem_u32(const void* p) {
    uint32_t a;
    asm("{ .reg .u64 t; cvta.to.shared.u64 t, %1; cvt.u32.u64 %0, t; }" : "=r"(a) : "l"(p));
    return a;
}

// All-scalar ldmatrix / mma macros (no array operands anywhere).
#define LDM4(r0, r1, r2, r3, addr)                                            \
    asm volatile("ldmatrix.sync.aligned.m8n8.x4.shared.b16 {%0,%1,%2,%3}, [%4];" \
                 : "=r"(r0), "=r"(r1), "=r"(r2), "=r"(r3) : "r"(addr))
#define MMA(c0, c1, c2, c3, a0, a1, a2, a3, b0, b1)                           \
    asm volatile("mma.sync.aligned.m16n8k16.row.col.f32.bf16.bf16.f32 "       \
                 "{%0,%1,%2,%3}, {%4,%5,%6,%7}, {%8,%9}, {%0,%1,%2,%3};"      \
                 : "+f"(c0), "+f"(c1), "+f"(c2), "+f"(c3)                     \
                 : "r"(a0), "r"(a1), "r"(a2), "r"(a3), "r"(b0), "r"(b1))

// smem tile: 64 bf16/row padded to 144 B -> 8 consecutive rows hit 8 distinct
// 16B banks (144 mod 128 = 16) => conflict-free ldmatrix and STS.
#define RSB   144
#define A_HI  0
#define A_LO  18432
#define B_HI  36864
#define B_LO  41472
#define SMB   46080   // <= 48 KB: static __shared__

// ---------------------------------------------------------------------------
// Prep kernels
// ---------------------------------------------------------------------------
__global__ void init_bar_kernel() { g_bar = 0u; }

__global__ void convx_kernel(const float* __restrict__ x) {
    size_t i = ((size_t)blockIdx.x * 256 + threadIdx.x) * 4;   // grid 16384
    float4 v = *(const float4*)(x + i);
    float vv[4] = {v.x, v.y, v.z, v.w};
#pragma unroll
    for (int m = 0; m < 4; m++) {
        __nv_bfloat16 hi = __float2bfloat16(vv[m]);
        g_x_hi[i + m] = hi;
        g_x_lo[i + m] = __float2bfloat16(vv[m] - __bfloat162float(hi));
    }
}

// in [K][N] fp32 -> (which ? g_Wt : g_Ut) hi/lo [N][K] bf16
__global__ __launch_bounds__(256) void transpose_split_kernel(const float* __restrict__ in,
                                                              int K, int N, int which) {
    __nv_bfloat16* ohi = which ? g_Wt_hi : g_Ut_hi;
    __nv_bfloat16* olo = which ? g_Wt_lo : g_Ut_lo;
    __shared__ float ts[32][33];
    int k0 = blockIdx.x * 32, n0 = blockIdx.y * 32;
    int r = threadIdx.x >> 5, c = threadIdx.x & 31;
#pragma unroll
    for (int i = 0; i < 4; i++)
        ts[r + i * 8][c] = in[(size_t)(k0 + r + i * 8) * N + n0 + c];
    __syncthreads();
#pragma unroll
    for (int i = 0; i < 4; i++) {
        int n = n0 + r + i * 8;
        float v = ts[c][r + i * 8];
        __nv_bfloat16 hi = __float2bfloat16(v);
        ohi[(size_t)n * K + k0 + c] = hi;
        olo[(size_t)n * K + k0 + c] = __float2bfloat16(v - __bfloat162float(hi));
    }
}

// ---------------------------------------------------------------------------
// xw MMA kernel: g_xz[t][b][n] = x_t @ W + bias.  Grid (128, 256) = (n-tile, t).
// M=128, N=32/CTA, K=512 (8 k-tiles). Same proven core as the step kernel,
// with straight n mapping (no gate scatter) and a bias epilogue.
// ---------------------------------------------------------------------------
__global__ __launch_bounds__(256) void xw_mma_kernel(const float* __restrict__ bias) {
    __shared__ __align__(16) char sm[SMB];
    const int tid = threadIdx.x, wid = tid >> 5, lane = tid & 31;
    const int n0 = blockIdx.x * 32;
    const int t  = blockIdx.y;
    const uint32_t sb = smem_u32(sm);
    const int m0 = wid * 16;

    const uint32_t a_off = (uint32_t)((m0 + (lane & 15)) * RSB + (lane >> 4) * 16);
    const uint32_t b_off = (uint32_t)((((lane >> 4) & 1) * 8 + (lane & 7)) * RSB
                                      + ((lane >> 3) & 1) * 16);

    float ci0 = 0.f, ci1 = 0.f, ci2 = 0.f, ci3 = 0.f;
    float cf0 = 0.f, cf1 = 0.f, cf2 = 0.f, cf3 = 0.f;
    float cg0 = 0.f, cg1 = 0.f, cg2 = 0.f, cg3 = 0.f;
    float co0 = 0.f, co1 = 0.f, co2 = 0.f, co3 = 0.f;

    const int ra = tid >> 3;                 // 0..31 A base row; also B row
    const int k8 = tid & 7;
    const size_t aoff = ((size_t)ra * T_ + t) * F_ + k8 * 8;
    const size_t arow = (size_t)32 * T_ * F_;   // +32 A rows
    const size_t boff = (size_t)(n0 + ra) * F_ + k8 * 8;
    const uint32_t sa  = (uint32_t)(ra * RSB + k8 * 16);

    uint4 p0, p1, p2, p3, p4, p5, p6, p7, q0, q1;
    p0 = *(const uint4*)(g_x_hi + aoff);
    p1 = *(const uint4*)(g_x_hi + aoff + arow);
    p2 = *(const uint4*)(g_x_hi + aoff + 2 * arow);
    p3 = *(const uint4*)(g_x_hi + aoff + 3 * arow);
    p4 = *(const uint4*)(g_x_lo + aoff);
    p5 = *(const uint4*)(g_x_lo + aoff + arow);
    p6 = *(const uint4*)(g_x_lo + aoff + 2 * arow);
    p7 = *(const uint4*)(g_x_lo + aoff + 3 * arow);
    q0 = *(const uint4*)(g_Wt_hi + boff);
    q1 = *(const uint4*)(g_Wt_lo + boff);

    for (int kt = 0; kt < 8; kt++) {
        __syncthreads();
        *(uint4*)(sm + A_HI + sa)            = p0;
        *(uint4*)(sm + A_HI + sa + 32 * RSB) = p1;
        *(uint4*)(sm + A_HI + sa + 64 * RSB) = p2;
        *(uint4*)(sm + A_HI + sa + 96 * RSB) = p3;
        *(uint4*)(sm + A_LO + sa)            = p4;
        *(uint4*)(sm + A_LO + sa + 32 * RSB) = p5;
        *(uint4*)(sm + A_LO + sa + 64 * RSB) = p6;
        *(uint4*)(sm + A_LO + sa + 96 * RSB) = p7;
        *(uint4*)(sm + B_HI + sa)            = q0;
        *(uint4*)(sm + B_LO + sa)            = q1;
        __syncthreads();
        if (kt + 1 < 8) {
            const size_t ko = (size_t)(kt + 1) * 64;
            p0 = *(const uint4*)(g_x_hi + aoff + ko);
            p1 = *(const uint4*)(g_x_hi + aoff + arow + ko);
            p2 = *(const uint4*)(g_x_hi + aoff + 2 * arow + ko);
            p3 = *(const uint4*)(g_x_hi + aoff + 3 * arow + ko);
            p4 = *(const uint4*)(g_x_lo + aoff + ko);
            p5 = *(const uint4*)(g_x_lo + aoff + arow + ko);
            p6 = *(const uint4*)(g_x_lo + aoff + 2 * arow + ko);
            p7 = *(const uint4*)(g_x_lo + aoff + 3 * arow + ko);
            q0 = *(const uint4*)(g_Wt_hi + boff + ko);
            q1 = *(const uint4*)(g_Wt_lo + boff + ko);
        }
#pragma unroll
        for (int s = 0; s < 4; s++) {
            uint32_t ah0, ah1, ah2, ah3, al0, al1, al2, al3;
            uint32_t b0, b1, b2, b3, d0, d1, d2, d3;
            LDM4(ah0, ah1, ah2, ah3, sb + A_HI + a_off + s * 32);
            LDM4(al0, al1, al2, al3, sb + A_LO + a_off + s * 32);
            LDM4(b0, b1, b2, b3, sb + B_HI + b_off + s * 32);
            LDM4(d0, d1, d2, d3, sb + B_LO + b_off + s * 32);
            MMA(ci0, ci1, ci2, ci3, ah0, ah1, ah2, ah3, b0, b1);
            MMA(ci0, ci1, ci2, ci3, ah0, ah1, ah2, ah3, d0, d1);
            MMA(ci0, ci1, ci2, ci3, al0, al1, al2, al3, b0, b1);
            MMA(cf0, cf1, cf2, cf3, ah0, ah1, ah2, ah3, b2, b3);
            MMA(cf0, cf1, cf2, cf3, ah0, ah1, ah2, ah3, d2, d3);
            MMA(cf0, cf1, cf2, cf3, al0, al1, al2, al3, b2, b3);
            LDM4(b0, b1, b2, b3, sb + B_HI + b_off + 16 * RSB + s * 32);
            LDM4(d0, d1, d2, d3, sb + B_LO + b_off + 16 * RSB + s * 32);
            MMA(cg0, cg1, cg2, cg3, ah0, ah1, ah2, ah3, b0, b1);
            MMA(cg0, cg1, cg2, cg3, ah0, ah1, ah2, ah3, d0, d1);
            MMA(cg0, cg1, cg2, cg3, al0, al1, al2, al3, b0, b1);
            MMA(co0, co1, co2, co3, ah0, ah1, ah2, ah3, b2, b3);
            MMA(co0, co1, co2, co3, ah0, ah1, ah2, ah3, d2, d3);
            MMA(co0, co1, co2, co3, al0, al1, al2, al3, b2, b3);
        }
    }

    // Epilogue: frag (rh, ch) -> b = m0 + (lane>>2) + 8*rh, n-col groups +0/8/16/24
    const int r = lane >> 2;
    const int cc = (lane & 3) * 2;
    float2 bv0 = *(const float2*)(bias + n0 + cc);
    float2 bv1 = *(const float2*)(bias + n0 + 8 + cc);
    float2 bv2 = *(const float2*)(bias + n0 + 16 + cc);
    float2 bv3 = *(const float2*)(bias + n0 + 24 + cc);
#pragma unroll
    for (int rh = 0; rh < 2; rh++) {
        int b = m0 + r + rh * 8;
        float* dst = g_xz + ((size_t)t * B_ + b) * G4 + n0;
        float vi0 = rh ? ci2 : ci0, vi1 = rh ? ci3 : ci1;
        float vf0 = rh ? cf2 : cf0, vf1 = rh ? cf3 : cf1;
        float vg0 = rh ? cg2 : cg0, vg1 = rh ? cg3 : cg1;
        float vo0 = rh ? co2 : co0, vo1 = rh ? co3 : co1;
        *(float2*)(dst + cc)      = make_float2(vi0 + bv0.x, vi1 + bv0.y);
        *(float2*)(dst + 8 + cc)  = make_float2(vf0 + bv1.x, vf1 + bv1.y);
        *(float2*)(dst + 16 + cc) = make_float2(vg0 + bv2.x, vg1 + bv2.y);
        *(float2*)(dst + 24 + cc) = make_float2(vo0 + bv3.x, vo1 + bv3.y);
    }
}

// ---------------------------------------------------------------------------
// Persistent recurrence kernel: grid 128 CTAs (all co-resident), t-loop inside,
// software grid barrier between steps. Same proven MMA core per step.
// ---------------------------------------------------------------------------
__global__ __launch_bounds__(256) void lstm_persistent(float* __restrict__ out) {
    __shared__ __align__(16) char sm[SMB];
    const int tid = threadIdx.x, wid = tid >> 5, lane = tid & 31;
    const int j0 = blockIdx.x * 8;
    const uint32_t sb = smem_u32(sm);
    const int m0 = wid * 16;

    const uint32_t a_off = (uint32_t)((m0 + (lane & 15)) * RSB + (lane >> 4) * 16);
    const uint32_t b_off = (uint32_t)((((lane >> 4) & 1) * 8 + (lane & 7)) * RSB
                                      + ((lane >> 3) & 1) * 16);

    const int ra = tid >> 3;               // A base row / B row
    const int k8 = tid & 7;
    const size_t aoff = (size_t)ra * H_ + k8 * 8;
    const size_t boff = (size_t)((ra >> 3) * H_ + j0 + (ra & 7)) * H_ + k8 * 8;
    const uint32_t sa  = (uint32_t)(ra * RSB + k8 * 16);

    const int r = lane >> 2;
    const int cc = (lane & 3) * 2;

    for (int t = 0; t < T_; t++) {
        float ci0 = 0.f, ci1 = 0.f, ci2 = 0.f, ci3 = 0.f;
        float cf0 = 0.f, cf1 = 0.f, cf2 = 0.f, cf3 = 0.f;
        float cg0 = 0.f, cg1 = 0.f, cg2 = 0.f, cg3 = 0.f;
        float co0 = 0.f, co1 = 0.f, co2 = 0.f, co3 = 0.f;

        if (t > 0) {
            uint4 p0, p1, p2, p3, p4, p5, p6, p7, q0, q1;
            p0 = *(const uint4*)(g_h_hi + aoff);
            p1 = *(const uint4*)(g_h_hi + aoff + (size_t)32 * H_);
            p2 = *(const uint4*)(g_h_hi + aoff + (size_t)64 * H_);
            p3 = *(const uint4*)(g_h_hi + aoff + (size_t)96 * H_);
            p4 = *(const uint4*)(g_h_lo + aoff);
            p5 = *(const uint4*)(g_h_lo + aoff + (size_t)32 * H_);
            p6 = *(const uint4*)(g_h_lo + aoff + (size_t)64 * H_);
            p7 = *(const uint4*)(g_h_lo + aoff + (size_t)96 * H_);
            q0 = *(const uint4*)(g_Ut_hi + boff);
            q1 = *(const uint4*)(g_Ut_lo + boff);

            for (int kt = 0; kt < 16; kt++) {
                __syncthreads();
                *(uint4*)(sm + A_HI + sa)            = p0;
                *(uint4*)(sm + A_HI + sa + 32 * RSB) = p1;
                *(uint4*)(sm + A_HI + sa + 64 * RSB) = p2;
                *(uint4*)(sm + A_HI + sa + 96 * RSB) = p3;
                *(uint4*)(sm + A_LO + sa)            = p4;
                *(uint4*)(sm + A_LO + sa + 32 * RSB) = p5;
                *(uint4*)(sm + A_LO + sa + 64 * RSB) = p6;
                *(uint4*)(sm + A_LO + sa + 96 * RSB) = p7;
                *(uint4*)(sm + B_HI + sa)            = q0;
                *(uint4*)(sm + B_LO + sa)            = q1;
                __syncthreads();
                if (kt + 1 < 16) {
                    const size_t ko = (size_t)(kt + 1) * 64;
                    p0 = *(const uint4*)(g_h_hi + aoff + ko);
                    p1 = *(const uint4*)(g_h_hi + aoff + (size_t)32 * H_ + ko);
                    p2 = *(const uint4*)(g_h_hi + aoff + (size_t)64 * H_ + ko);
                    p3 = *(const uint4*)(g_h_hi + aoff + (size_t)96 * H_ + ko);
                    p4 = *(const uint4*)(g_h_lo + aoff + ko);
                    p5 = *(const uint4*)(g_h_lo + aoff + (size_t)32 * H_ + ko);
                    p6 = *(const uint4*)(g_h_lo + aoff + (size_t)64 * H_ + ko);
                    p7 = *(const uint4*)(g_h_lo + aoff + (size_t)96 * H_ + ko);
                    q0 = *(const uint4*)(g_Ut_hi + boff + ko);
                    q1 = *(const uint4*)(g_Ut_lo + boff + ko);
                }
#pragma unroll
                for (int s = 0; s < 4; s++) {
                    uint32_t ah0, ah1, ah2, ah3, al0, al1, al2, al3;
                    uint32_t b0, b1, b2, b3, d0, d1, d2, d3;
                    LDM4(ah0, ah1, ah2, ah3, sb + A_HI + a_off + s * 32);
                    LDM4(al0, al1, al2, al3, sb + A_LO + a_off + s * 32);
                    LDM4(b0, b1, b2, b3, sb + B_HI + b_off + s * 32);
                    LDM4(d0, d1, d2, d3, sb + B_LO + b_off + s * 32);
                    MMA(ci0, ci1, ci2, ci3, ah0, ah1, ah2, ah3, b0, b1);
                    MMA(ci0, ci1, ci2, ci3, ah0, ah1, ah2, ah3, d0, d1);
                    MMA(ci0, ci1, ci2, ci3, al0, al1, al2, al3, b0, b1);
                    MMA(cf0, cf1, cf2, cf3, ah0, ah1, ah2, ah3, b2, b3);
                    MMA(cf0, cf1, cf2, cf3, ah0, ah1, ah2, ah3, d2, d3);
                    MMA(cf0, cf1, cf2, cf3, al0, al1, al2, al3, b2, b3);
                    LDM4(b0, b1, b2, b3, sb + B_HI + b_off + 16 * RSB + s * 32);
                    LDM4(d0, d1, d2, d3, sb + B_LO + b_off + 16 * RSB + s * 32);
                    MMA(cg0, cg1, cg2, cg3, ah0, ah1, ah2, ah3, b0, b1);
                    MMA(cg0, cg1, cg2, cg3, ah0, ah1, ah2, ah3, d0, d1);
                    MMA(cg0, cg1, cg2, cg3, al0, al1, al2, al3, b0, b1);
                    MMA(co0, co1, co2, co3, ah0, ah1, ah2, ah3, b2, b3);
                    MMA(co0, co1, co2, co3, ah0, ah1, ah2, ah3, d2, d3);
                    MMA(co0, co1, co2, co3, al0, al1, al2, al3, b2, b3);
                }
            }
        }

        // Gates + state update
        const int first = (t == 0);
#pragma unroll
        for (int rh = 0; rh < 2; rh++) {
            int b = m0 + r + rh * 8;
            const float* xzp = g_xz + ((size_t)t * B_ + b) * G4;
#pragma unroll
            for (int ch = 0; ch < 2; ch++) {
                int j = j0 + cc + ch;
                float zi, zf, zg, zo;
                if (rh == 0 && ch == 0) { zi = ci0; zf = cf0; zg = cg0; zo = co0; }
                else if (rh == 0)       { zi = ci1; zf = cf1; zg = cg1; zo = co1; }
                else if (ch == 0)       { zi = ci2; zf = cf2; zg = cg2; zo = co2; }
                else                    { zi = ci3; zf = cf3; zg = cg3; zo = co3; }
                zi += xzp[0 * H_ + j];
                zf += xzp[1 * H_ + j];
                zg += xzp[2 * H_ + j];
                zo += xzp[3 * H_ + j];
                float ig = fast_sigmoid(zi);
                float fg = fast_sigmoid(zf);
                float gg = tanhf(zg);
                float og = fast_sigmoid(zo);
                size_t idx = (size_t)b * H_ + j;
                float c_old = first ? 0.0f : g_c[idx];
                float cv = fg * c_old + ig * gg;
                float hv = og * tanhf(cv);
                g_c[idx] = cv;
                out[(size_t)t * B_ * H_ + idx] = hv;
                __nv_bfloat16 hi = __float2bfloat16(hv);
                g_h_hi[idx] = hi;
                g_h_lo[idx] = __float2bfloat16(hv - __bfloat162float(hi));
            }
        }

        // Grid barrier (skip after last step). Bounded spin: a broken barrier
        // yields a wrong answer + profile, not a hung container.
        if (t + 1 < T_) {
            __syncthreads();
            if (tid == 0) {
                __threadfence();                       // release: h writes -> L2
                atomicAdd(&g_bar, 1u);
                unsigned target = (unsigned)(t + 1) * 128u;
                volatile unsigned* vb = &g_bar;
                int spins = 0;
                while (*vb < target && spins < 2000000) { spins++; __nanosleep(60); }
            }
            __syncthreads();
            __threadfence();                           // acquire: drop stale L1 h
        }
    }
}

// ---------------------------------------------------------------------------
extern "C" void kernel_launch(void* const* d_in, const int* in_sizes, int n_in,
                              void* d_out, int out_size) {
    const float* x = (const float*)d_in[0];   // [B, T, F]
    const float* W = (const float*)d_in[1];   // [F, 4H]
    const float* U = (const float*)d_in[2];   // [H, 4H]
    const float* b = (const float*)d_in[3];   // [4H]
    float* out = (float*)d_out;               // [T, B, H]
    (void)in_sizes; (void)n_in; (void)out_size;

    // Prep (off the serial path)
    init_bar_kernel<<<1, 1>>>();
    convx_kernel<<<16384, 256>>>(x);
    transpose_split_kernel<<<dim3(F_ / 32, G4 / 32), 256>>>(W, F_, G4, 1);
    transpose_split_kernel<<<dim3(H_ / 32, G4 / 32), 256>>>(U, H_, G4, 0);

    // Phase 1: xz = x@W + bias (tensor cores)
    xw_mma_kernel<<<dim3(128, 256), 256>>>(b);

    // Phase 2: full recurrence in ONE persistent launch
    lstm_persistent<<<128, 256>>>(out);
}